// round 2
// baseline (speedup 1.0000x reference)
#include <cuda_runtime.h>
#include <math.h>

// Problem constants (from reference setup_inputs): B=32, C=3, H=W=512
#define BB 32
#define CC 3
#define HH 512
#define WW 512

// Per-batch affine 2x2 (translation is exactly zero in the reference's
// transposed-matrix convention): [m00 m01 m10 m11]
__device__ float d_theta[BB][4];

__global__ void compute_theta_kernel(const float* __restrict__ thetas,
                                     const float* __restrict__ l1s,
                                     const float* __restrict__ l2s) {
    int b = threadIdx.x;
    if (b >= BB) return;
    // th = -theta; M = R(th)^-1 * diag(1/l1, 1/l2) * R(th)
    float th = -thetas[b];
    float c = cosf(th);
    float s = sinf(th);
    float il1 = 1.0f / l1s[b];
    float il2 = 1.0f / l2s[b];
    float m00 = c * c * il1 + s * s * il2;
    float m11 = s * s * il1 + c * c * il2;
    float m01 = c * s * (il2 - il1);
    d_theta[b][0] = m00;
    d_theta[b][1] = m01;
    d_theta[b][2] = m01;  // m10 == m01 (symmetric)
    d_theta[b][3] = m11;
}

__global__ __launch_bounds__(256) void warp_kernel(const float* __restrict__ x,
                                                   float* __restrict__ out) {
    int px = blockIdx.x * blockDim.x + threadIdx.x;
    int py = blockIdx.y * blockDim.y + threadIdx.y;
    int b  = blockIdx.z;
    if (px >= WW || py >= HH) return;

    float m00 = d_theta[b][0];
    float m01 = d_theta[b][1];
    float m10 = d_theta[b][2];
    float m11 = d_theta[b][3];

    // normalized coords of output pixel center
    float X = ((float)px + 0.5f) * (2.0f / (float)WW) - 1.0f;
    float Y = ((float)py + 0.5f) * (2.0f / (float)HH) - 1.0f;

    // warped normalized coords (no translation term)
    float gxn = m00 * X + m01 * Y;
    float gyn = m10 * X + m11 * Y;

    // to pixel coords
    float gx = (gxn + 1.0f) * ((float)WW * 0.5f) - 0.5f;
    float gy = (gyn + 1.0f) * ((float)HH * 0.5f) - 0.5f;

    float x0f = floorf(gx);
    float y0f = floorf(gy);
    int x0 = (int)x0f;
    int y0 = (int)y0f;
    int x1 = x0 + 1;
    int y1 = y0 + 1;

    float wx1 = gx - x0f;
    float wx0 = 1.0f - wx1;
    float wy1 = gy - y0f;
    float wy0 = 1.0f - wy1;

    // border masks (zeros padding)
    float mx0 = (x0 >= 0 && x0 < WW) ? 1.0f : 0.0f;
    float mx1 = (x1 >= 0 && x1 < WW) ? 1.0f : 0.0f;
    float my0 = (y0 >= 0 && y0 < HH) ? 1.0f : 0.0f;
    float my1 = (y1 >= 0 && y1 < HH) ? 1.0f : 0.0f;

    float w00 = wy0 * wx0 * my0 * mx0;
    float w01 = wy0 * wx1 * my0 * mx1;
    float w10 = wy1 * wx0 * my1 * mx0;
    float w11 = wy1 * wx1 * my1 * mx1;

    // clamped indices for the gathers
    int xc0 = min(max(x0, 0), WW - 1);
    int xc1 = min(max(x1, 0), WW - 1);
    int yc0 = min(max(y0, 0), HH - 1);
    int yc1 = min(max(y1, 0), HH - 1);

    int i00 = yc0 * WW + xc0;
    int i01 = yc0 * WW + xc1;
    int i10 = yc1 * WW + xc0;
    int i11 = yc1 * WW + xc1;

    const float* xb = x + (size_t)b * CC * HH * WW;
    size_t obase = ((size_t)b * CC) * HH * WW + (size_t)py * WW + px;

#pragma unroll
    for (int c = 0; c < CC; c++) {
        const float* p = xb + (size_t)c * HH * WW;
        float v = w00 * __ldg(p + i00) + w01 * __ldg(p + i01) +
                  w10 * __ldg(p + i10) + w11 * __ldg(p + i11);
        out[obase + (size_t)c * HH * WW] = v;
    }
}

extern "C" void kernel_launch(void* const* d_in, const int* in_sizes, int n_in,
                              void* d_out, int out_size) {
    const float* x      = (const float*)d_in[0];
    const float* thetas = (const float*)d_in[1];
    const float* l1s    = (const float*)d_in[2];
    const float* l2s    = (const float*)d_in[3];
    float* out = (float*)d_out;

    compute_theta_kernel<<<1, BB>>>(thetas, l1s, l2s);

    dim3 block(32, 8, 1);
    dim3 grid(WW / 32, HH / 8, BB);
    warp_kernel<<<grid, block>>>(x, out);
}

// round 4
// speedup vs baseline: 1.5033x; 1.5033x over previous
#include <cuda_runtime.h>
#include <math.h>

// Problem constants: B=32, C=3, H=W=512
#define BB 32
#define CC 3
#define HH 512
#define WW 512

// Per-batch affine 2x2 (translation exactly zero): [m00 m01 m10 m11]
__device__ float d_theta[BB][4];

__global__ void compute_theta_kernel(const float* __restrict__ thetas,
                                     const float* __restrict__ l1s,
                                     const float* __restrict__ l2s) {
    int b = threadIdx.x;
    if (b >= BB) return;
    float th = -thetas[b];
    float c = cosf(th);
    float s = sinf(th);
    float il1 = 1.0f / l1s[b];
    float il2 = 1.0f / l2s[b];
    float m00 = c * c * il1 + s * s * il2;
    float m11 = s * s * il1 + c * c * il2;
    float m01 = c * s * (il2 - il1);
    d_theta[b][0] = m00;
    d_theta[b][1] = m01;
    d_theta[b][2] = m01;
    d_theta[b][3] = m11;
}

// Each thread computes 4 consecutive output pixels (one float4 store per channel).
__global__ __launch_bounds__(256) void warp_kernel(const float* __restrict__ x,
                                                   float* __restrict__ out) {
    int tx = blockIdx.x * blockDim.x + threadIdx.x;  // 0..127 (x/4)
    int py = blockIdx.y * blockDim.y + threadIdx.y;
    int b  = blockIdx.z;
    int px0 = tx * 4;

    float m00 = d_theta[b][0];
    float m01 = d_theta[b][1];
    float m10 = d_theta[b][2];
    float m11 = d_theta[b][3];

    // Normalized coords of first pixel center
    float X = ((float)px0 + 0.5f) * (2.0f / (float)WW) - 1.0f;
    float Y = ((float)py + 0.5f) * (2.0f / (float)HH) - 1.0f;

    // Pixel-space sample coords; per-output-pixel step is (m00, m10)
    float gx = (m00 * X + m01 * Y + 1.0f) * ((float)WW * 0.5f) - 0.5f;
    float gy = (m10 * X + m11 * Y + 1.0f) * ((float)HH * 0.5f) - 0.5f;

    float w00[4], w01[4], w10[4], w11[4];
    int   i00[4], i01[4], i10[4], i11[4];

#pragma unroll
    for (int k = 0; k < 4; k++) {
        float x0f = floorf(gx);
        float y0f = floorf(gy);
        int x0 = (int)x0f;
        int y0 = (int)y0f;
        int x1 = x0 + 1;
        int y1 = y0 + 1;

        float wx1 = gx - x0f;
        float wx0 = 1.0f - wx1;
        float wy1 = gy - y0f;
        float wy0 = 1.0f - wy1;

        float mx0 = (x0 >= 0 && x0 < WW) ? 1.0f : 0.0f;
        float mx1 = (x1 >= 0 && x1 < WW) ? 1.0f : 0.0f;
        float my0 = (y0 >= 0 && y0 < HH) ? 1.0f : 0.0f;
        float my1 = (y1 >= 0 && y1 < HH) ? 1.0f : 0.0f;

        w00[k] = wy0 * wx0 * my0 * mx0;
        w01[k] = wy0 * wx1 * my0 * mx1;
        w10[k] = wy1 * wx0 * my1 * mx0;
        w11[k] = wy1 * wx1 * my1 * mx1;

        int xc0 = min(max(x0, 0), WW - 1);
        int xc1 = min(max(x1, 0), WW - 1);
        int yc0 = min(max(y0, 0), HH - 1);
        int yc1 = min(max(y1, 0), HH - 1);

        i00[k] = yc0 * WW + xc0;
        i01[k] = yc0 * WW + xc1;
        i10[k] = yc1 * WW + xc0;
        i11[k] = yc1 * WW + xc1;

        gx += m00;
        gy += m10;
    }

    const float* xb = x + (size_t)b * CC * HH * WW;
    float* ob = out + ((size_t)b * CC) * HH * WW + (size_t)py * WW + px0;

#pragma unroll
    for (int c = 0; c < CC; c++) {
        const float* p = xb + (size_t)c * HH * WW;
        float4 v;
        float* vv = (float*)&v;
#pragma unroll
        for (int k = 0; k < 4; k++) {
            float acc = 0.0f;
            if (w00[k] != 0.0f) acc += w00[k] * __ldg(p + i00[k]);
            if (w01[k] != 0.0f) acc += w01[k] * __ldg(p + i01[k]);
            if (w10[k] != 0.0f) acc += w10[k] * __ldg(p + i10[k]);
            if (w11[k] != 0.0f) acc += w11[k] * __ldg(p + i11[k]);
            vv[k] = acc;
        }
        *(float4*)(ob + (size_t)c * HH * WW) = v;
    }
}

extern "C" void kernel_launch(void* const* d_in, const int* in_sizes, int n_in,
                              void* d_out, int out_size) {
    const float* x      = (const float*)d_in[0];
    const float* thetas = (const float*)d_in[1];
    const float* l1s    = (const float*)d_in[2];
    const float* l2s    = (const float*)d_in[3];
    float* out = (float*)d_out;

    compute_theta_kernel<<<1, BB>>>(thetas, l1s, l2s);

    dim3 block(32, 8, 1);                 // 32 threads * 4 px = 128 px in x
    dim3 grid(WW / 128, HH / 8, BB);      // 4 x 64 x 32
    warp_kernel<<<grid, block>>>(x, out);
}